// round 2
// baseline (speedup 1.0000x reference)
#include <cuda_runtime.h>
#include <math.h>

#define NN 50000
#define NE 1600000
#define ET (NE + NN)        // edges + self loops = 1,650,000
#define NG 64

// ---------------- device scratch (no allocation allowed) ----------------
__device__ int      g_is64;
__device__ float    g_xl[NN * 64];
__device__ float    g_xr[NN * 64];
__device__ float    g_num[NN * 64];
__device__ float    g_h[NN * 64];
__device__ float    g_scores[ET * 2];
__device__ float    g_expsum[NN * 2];
__device__ unsigned g_max[NN * 2];
__device__ float    g_pool[NG * 64];
__device__ float    g_cnt[NG];

// monotonic float <-> uint encoding for atomicMax on floats
__device__ __forceinline__ unsigned fenc(float f) {
    unsigned b = __float_as_uint(f);
    return (b & 0x80000000u) ? ~b : (b | 0x80000000u);
}
__device__ __forceinline__ float fdec(unsigned u) {
    unsigned b = (u & 0x80000000u) ? (u & 0x7FFFFFFFu) : ~u;
    return __uint_as_float(b);
}

// Detect whether edge_index is int64 (odd int32 words all zero) or int32.
__global__ void k_detect(const void* ei) {
    if (threadIdx.x == 0) {
        const int* p = (const int*)ei;
        int nz = 0;
        #pragma unroll 4
        for (int i = 0; i < 128; i++) nz |= p[2 * i + 1];
        g_is64 = (nz == 0) ? 1 : 0;
    }
}

__device__ __forceinline__ void edge_sd(const void* ei, int e, int is64, int& s, int& d) {
    if (e < NE) {
        if (is64) {
            const long long* p = (const long long*)ei;
            s = (int)p[e]; d = (int)p[NE + e];
        } else {
            const int* p = (const int*)ei;
            s = p[e]; d = p[NE + e];
        }
    } else {
        s = d = e - NE;   // self loop
    }
}

__global__ void k_init(int full) {
    int i = blockIdx.x * blockDim.x + threadIdx.x;
    if (i < NN * 64) g_num[i] = 0.f;
    if (i < NN * 2) { g_expsum[i] = 0.f; g_max[i] = 0u; }
    if (full) {
        if (i < NG * 64) g_pool[i] = 0.f;
        if (i < NG)      g_cnt[i]  = 0.f;
    }
}

// Y[N,64] = X[N,K] @ W[K,64].  256 threads/block, 32 rows/block.
template<int K>
__global__ void k_gemm(const float* __restrict__ X, const float* __restrict__ W,
                       float* __restrict__ Y) {
    __shared__ float Ws[K * 64];
    __shared__ float xs[32 * K];
    int tid = threadIdx.x;
    int n0  = blockIdx.x * 32;
    for (int i = tid; i < K * 64; i += 256) Ws[i] = W[i];
    for (int i = tid; i < 32 * K; i += 256) {
        int n = i / K, k = i - n * K;
        xs[i] = (n0 + n < NN) ? X[(size_t)(n0 + n) * K + k] : 0.f;
    }
    __syncthreads();
    int n = tid >> 3, c0 = (tid & 7) * 8;
    float acc[8] = {0, 0, 0, 0, 0, 0, 0, 0};
    const float* xrow = &xs[n * K];
    #pragma unroll 4
    for (int k = 0; k < K; k++) {
        float xv = xrow[k];
        float4 a = *(const float4*)&Ws[k * 64 + c0];
        float4 b = *(const float4*)&Ws[k * 64 + c0 + 4];
        acc[0] += xv * a.x; acc[1] += xv * a.y; acc[2] += xv * a.z; acc[3] += xv * a.w;
        acc[4] += xv * b.x; acc[5] += xv * b.y; acc[6] += xv * b.z; acc[7] += xv * b.w;
    }
    if (n0 + n < NN) {
        float4* y4 = (float4*)&Y[(size_t)(n0 + n) * 64 + c0];
        y4[0] = make_float4(acc[0], acc[1], acc[2], acc[3]);
        y4[1] = make_float4(acc[4], acc[5], acc[6], acc[7]);
    }
}

// One warp per edge: scores + segment max.
template<int NH>
__global__ void k_score(const void* ei, const float* __restrict__ att,
                        const float* __restrict__ xl, const float* __restrict__ xr) {
    int w    = (blockIdx.x * blockDim.x + threadIdx.x) >> 5;
    int lane = threadIdx.x & 31;
    if (w >= ET) return;
    int is64 = g_is64;
    int s, d; edge_sd(ei, w, is64, s, d);
    float l0 = xl[(size_t)s * 64 + lane],      l1 = xl[(size_t)s * 64 + 32 + lane];
    float r0 = xr[(size_t)d * 64 + lane],      r1 = xr[(size_t)d * 64 + 32 + lane];
    float v0 = l0 + r0; v0 = v0 > 0.f ? v0 : 0.2f * v0;
    float v1 = l1 + r1; v1 = v1 > 0.f ? v1 : 0.2f * v1;
    float a0 = v0 * att[lane];
    float a1 = v1 * att[32 + lane];
    if (NH == 1) a0 += a1;
    #pragma unroll
    for (int off = 16; off; off >>= 1) {
        a0 += __shfl_down_sync(0xffffffffu, a0, off);
        if (NH == 2) a1 += __shfl_down_sync(0xffffffffu, a1, off);
    }
    if (lane == 0) {
        g_scores[w * NH] = a0;
        atomicMax(&g_max[d * NH], fenc(a0));
        if (NH == 2) {
            g_scores[w * 2 + 1] = a1;
            atomicMax(&g_max[d * 2 + 1], fenc(a1));
        }
    }
}

// One warp per edge: exp, segment sum, and numerator accumulation.
template<int NH>
__global__ void k_accum(const void* ei, const float* __restrict__ xl) {
    int w    = (blockIdx.x * blockDim.x + threadIdx.x) >> 5;
    int lane = threadIdx.x & 31;
    if (w >= ET) return;
    int is64 = g_is64;
    int s, d; edge_sd(ei, w, is64, s, d);
    float e0 = 0.f, e1 = 0.f;
    if (lane == 0) {
        float m0 = fdec(g_max[d * NH]);
        e0 = expf(g_scores[w * NH] - m0);
        atomicAdd(&g_expsum[d * NH], e0);
        if (NH == 2) {
            float m1 = fdec(g_max[d * 2 + 1]);
            e1 = expf(g_scores[w * 2 + 1] - m1);
            atomicAdd(&g_expsum[d * 2 + 1], e1);
        }
    }
    e0 = __shfl_sync(0xffffffffu, e0, 0);
    e1 = (NH == 2) ? __shfl_sync(0xffffffffu, e1, 0) : e0;
    float x0 = xl[(size_t)s * 64 + lane];
    float x1 = xl[(size_t)s * 64 + 32 + lane];
    atomicAdd(&g_num[(size_t)d * 64 + lane],      e0 * x0);
    atomicAdd(&g_num[(size_t)d * 64 + 32 + lane], e1 * x1);
}

// out = elu(num/(sum+1e-16) + bias)
template<int NH>
__global__ void k_finish(const float* __restrict__ bias, float* __restrict__ out) {
    int i = blockIdx.x * blockDim.x + threadIdx.x;
    if (i >= NN * 64) return;
    int n = i >> 6, c = i & 63;
    int h = (NH == 2) ? (c >> 5) : 0;
    float v = g_num[i] / (g_expsum[n * NH + h] + 1e-16f) + bias[c];
    out[i] = v > 0.f ? v : expm1f(v);
}

__global__ void k_pool(const void* batch) {
    int i = blockIdx.x * blockDim.x + threadIdx.x;
    if (i >= NN * 64) return;
    int n = i >> 6, c = i & 63;
    int is64 = g_is64;
    int g = is64 ? (int)((const long long*)batch)[n] : ((const int*)batch)[n];
    atomicAdd(&g_pool[g * 64 + c], g_h[i]);
    if (c == 0) atomicAdd(&g_cnt[g], 1.0f);
}

__global__ void k_final(const float* __restrict__ lw, const float* __restrict__ lb,
                        float* __restrict__ out) {
    int tid = threadIdx.x;
    if (tid >= 128) return;
    int g = tid >> 1, k = tid & 1;
    float cnt = g_cnt[g]; cnt = cnt > 1.f ? cnt : 1.f;
    float s = 0.f;
    #pragma unroll 8
    for (int c = 0; c < 64; c++) s += (g_pool[g * 64 + c] / cnt) * lw[c * 2 + k];
    out[g * 2 + k] = s + lb[k];
}

extern "C" void kernel_launch(void* const* d_in, const int* in_sizes, int n_in,
                              void* d_out, int out_size) {
    const float* x    = (const float*)d_in[0];
    const void*  ei   = d_in[1];
    const void*  batch= d_in[2];
    const float* Wl1  = (const float*)d_in[3];
    const float* Wr1  = (const float*)d_in[4];
    const float* att1 = (const float*)d_in[5];
    const float* b1   = (const float*)d_in[6];
    const float* Wl2  = (const float*)d_in[7];
    const float* Wr2  = (const float*)d_in[8];
    const float* att2 = (const float*)d_in[9];
    const float* b2   = (const float*)d_in[10];
    const float* lw   = (const float*)d_in[11];
    const float* lb   = (const float*)d_in[12];
    float* out = (float*)d_out;

    float *xl, *xr, *h;
    cudaGetSymbolAddress((void**)&xl, g_xl);
    cudaGetSymbolAddress((void**)&xr, g_xr);
    cudaGetSymbolAddress((void**)&h,  g_h);

    const int TB = 256;
    const int GB_NODE = (NN * 64 + TB - 1) / TB;          // 12500
    const int GB_EDGE = (ET + 7) / 8;                     // 206250 (8 warps/block)
    const int GB_GEMM = (NN + 31) / 32;                   // 1563

    k_detect<<<1, 32>>>(ei);
    k_init<<<GB_NODE, TB>>>(1);

    // ---- layer 1 (heads=2, ch=32) ----
    k_gemm<128><<<GB_GEMM, TB>>>(x, Wl1, xl);
    k_gemm<128><<<GB_GEMM, TB>>>(x, Wr1, xr);
    k_score<2><<<GB_EDGE, TB>>>(ei, att1, xl, xr);
    k_accum<2><<<GB_EDGE, TB>>>(ei, xl);
    k_finish<2><<<GB_NODE, TB>>>(b1, h);

    // ---- layer 2 (heads=1, ch=64) ----
    k_init<<<GB_NODE, TB>>>(0);
    k_gemm<64><<<GB_GEMM, TB>>>(h, Wl2, xl);
    k_gemm<64><<<GB_GEMM, TB>>>(h, Wr2, xr);
    k_score<1><<<GB_EDGE, TB>>>(ei, att2, xl, xr);
    k_accum<1><<<GB_EDGE, TB>>>(ei, xl);
    k_finish<1><<<GB_NODE, TB>>>(b2, h);

    // ---- pooling + classifier ----
    k_pool<<<GB_NODE, TB>>>(batch);
    k_final<<<1, 128>>>(lw, lb, out);
}

// round 3
// speedup vs baseline: 2.1047x; 2.1047x over previous
#include <cuda_runtime.h>
#include <math.h>

#define NN 50000
#define NE 1600000
#define NG 64

// ---------------- device scratch ----------------
__device__ int   g_is64;
__device__ float g_xl[NN * 64];
__device__ float g_xr[NN * 64];
__device__ float g_h [NN * 64];
__device__ int   g_deg[NN];
__device__ int   g_off[NN + 1];
__device__ int   g_wp [NN];
__device__ int   g_csr[NE];
__device__ float g_pool[NG * 64];
__device__ float g_cnt[NG];

// Detect int64 vs int32 edge_index (odd int32 words all zero for int64).
__global__ void k_detect(const void* ei) {
    if (threadIdx.x == 0) {
        const int* p = (const int*)ei;
        int nz = 0;
        #pragma unroll 4
        for (int i = 0; i < 128; i++) nz |= p[2 * i + 1];
        g_is64 = (nz == 0) ? 1 : 0;
    }
}

__device__ __forceinline__ int edge_src(const void* ei, int e, int is64) {
    return is64 ? (int)((const long long*)ei)[e] : ((const int*)ei)[e];
}
__device__ __forceinline__ int edge_dst(const void* ei, int e, int is64) {
    return is64 ? (int)((const long long*)ei)[NE + e] : ((const int*)ei)[NE + e];
}

__global__ void k_zero() {
    int i = blockIdx.x * blockDim.x + threadIdx.x;
    if (i < NN) g_deg[i] = 0;
    if (i < NG * 64) g_pool[i] = 0.f;
    if (i < NG) g_cnt[i] = 0.f;
}

__global__ void k_hist(const void* ei) {
    int e = blockIdx.x * blockDim.x + threadIdx.x;
    if (e < NE) atomicAdd(&g_deg[edge_dst(ei, e, g_is64)], 1);
}

// Single-block scan of g_deg -> g_off / g_wp.
__global__ void k_scan() {
    __shared__ int part[1024];
    const int C = (NN + 1023) / 1024;   // 49
    int t = threadIdx.x;
    int base = t * C;
    int s = 0;
    for (int i = 0; i < C; i++) { int idx = base + i; if (idx < NN) s += g_deg[idx]; }
    part[t] = s;
    __syncthreads();
    for (int off = 1; off < 1024; off <<= 1) {
        int v = (t >= off) ? part[t - off] : 0;
        __syncthreads();
        part[t] += v;
        __syncthreads();
    }
    int run = (t == 0) ? 0 : part[t - 1];
    for (int i = 0; i < C; i++) {
        int idx = base + i;
        if (idx < NN) { g_off[idx] = run; g_wp[idx] = run; run += g_deg[idx]; }
    }
    if (t == 1023) g_off[NN] = run;
}

__global__ void k_scatter(const void* ei) {
    int e = blockIdx.x * blockDim.x + threadIdx.x;
    if (e < NE) {
        int is64 = g_is64;
        int d = edge_dst(ei, e, is64);
        int s = edge_src(ei, e, is64);
        int p = atomicAdd(&g_wp[d], 1);
        g_csr[p] = s;
    }
}

// Y[N,64] = X[N,K] @ W[K,64]. 256 threads, 64 rows/block, 2 rows x 8 cols per thread.
template<int K>
__global__ void k_gemm2(const float* __restrict__ X, const float* __restrict__ W,
                        float* __restrict__ Y) {
    extern __shared__ float sm[];
    float* Ws = sm;            // K*64
    float* xs = sm + K * 64;   // 64*K
    int tid = threadIdx.x;
    int n0  = blockIdx.x * 64;
    for (int i = tid; i < K * 16; i += 256)
        ((float4*)Ws)[i] = ((const float4*)W)[i];
    for (int i = tid; i < 16 * K; i += 256) {  // 64*K/4 float4s
        int n = i / (K / 4), kk = i % (K / 4);
        int row = n0 + n;
        ((float4*)xs)[i] = (row < NN) ? ((const float4*)X)[(size_t)row * (K / 4) + kk]
                                      : make_float4(0.f, 0.f, 0.f, 0.f);
    }
    __syncthreads();
    int n = tid >> 3, c0 = (tid & 7) * 8;
    float a[16];
    #pragma unroll
    for (int i = 0; i < 16; i++) a[i] = 0.f;
    #pragma unroll 4
    for (int k = 0; k < K; k++) {
        float4 w0 = *(const float4*)&Ws[k * 64 + c0];
        float4 w1 = *(const float4*)&Ws[k * 64 + c0 + 4];
        float xa = xs[n * K + k];
        float xb = xs[(n + 32) * K + k];
        a[0] += xa * w0.x; a[1] += xa * w0.y; a[2] += xa * w0.z; a[3] += xa * w0.w;
        a[4] += xa * w1.x; a[5] += xa * w1.y; a[6] += xa * w1.z; a[7] += xa * w1.w;
        a[8] += xb * w0.x; a[9] += xb * w0.y; a[10]+= xb * w0.z; a[11]+= xb * w0.w;
        a[12]+= xb * w1.x; a[13]+= xb * w1.y; a[14]+= xb * w1.z; a[15]+= xb * w1.w;
    }
    int ra = n0 + n, rb = n0 + n + 32;
    if (ra < NN) {
        float4* y = (float4*)&Y[(size_t)ra * 64 + c0];
        y[0] = make_float4(a[0], a[1], a[2], a[3]);
        y[1] = make_float4(a[4], a[5], a[6], a[7]);
    }
    if (rb < NN) {
        float4* y = (float4*)&Y[(size_t)rb * 64 + c0];
        y[0] = make_float4(a[8], a[9], a[10], a[11]);
        y[1] = make_float4(a[12], a[13], a[14], a[15]);
    }
}

// Fused GATv2: one warp per dst node, online softmax, no atomics.
// Lane holds channel pair (2*lane, 2*lane+1). For NH=2 head = lane>>4,
// and the 4-step xor butterfly produces per-head sums in place.
template<int NH>
__global__ void k_gat(const float* __restrict__ xl, const float* __restrict__ xr,
                      const float* __restrict__ att, const float* __restrict__ bias,
                      float* __restrict__ out) {
    int w    = (blockIdx.x * blockDim.x + threadIdx.x) >> 5;
    int lane = threadIdx.x & 31;
    if (w >= NN) return;
    int d = w;
    float2 at  = ((const float2*)att)[lane];
    float2 xrd = ((const float2*)xr)[(size_t)d * 32 + lane];
    float2 bi  = ((const float2*)bias)[lane];

    float m = -3e38f, ssum = 0.f, accx = 0.f, accy = 0.f;

#define GAT_PROCESS(cur)                                                      \
    {                                                                         \
        float vx = (cur).x + xrd.x; vx = vx > 0.f ? vx : 0.2f * vx;           \
        float vy = (cur).y + xrd.y; vy = vy > 0.f ? vy : 0.2f * vy;           \
        float p = vx * at.x + vy * at.y;                                      \
        p += __shfl_xor_sync(0xffffffffu, p, 1);                              \
        p += __shfl_xor_sync(0xffffffffu, p, 2);                              \
        p += __shfl_xor_sync(0xffffffffu, p, 4);                              \
        p += __shfl_xor_sync(0xffffffffu, p, 8);                              \
        if (NH == 1) p += __shfl_xor_sync(0xffffffffu, p, 16);                \
        float nm  = fmaxf(m, p);                                              \
        float sc  = __expf(m - nm);                                           \
        float wgt = __expf(p - nm);                                           \
        ssum = ssum * sc + wgt;                                               \
        accx = accx * sc + wgt * (cur).x;                                     \
        accy = accy * sc + wgt * (cur).y;                                     \
        m = nm;                                                               \
    }

    // self loop
    {
        float2 cur = ((const float2*)xl)[(size_t)d * 32 + lane];
        GAT_PROCESS(cur);
    }
    int start = g_off[d], end = g_off[d + 1];
    for (int j = start; j < end; j += 32) {
        int nsub = min(32, end - j);
        int sv = (j + lane < end) ? g_csr[j + lane] : 0;
        int s0 = __shfl_sync(0xffffffffu, sv, 0);
        float2 xv = ((const float2*)xl)[(size_t)s0 * 32 + lane];
        for (int k = 0; k < nsub; k++) {
            float2 cur = xv;
            if (k + 1 < nsub) {
                int sn = __shfl_sync(0xffffffffu, sv, k + 1);
                xv = ((const float2*)xl)[(size_t)sn * 32 + lane];
            }
            GAT_PROCESS(cur);
        }
    }
#undef GAT_PROCESS

    float inv = 1.f / (ssum + 1e-16f);
    float ox = accx * inv + bi.x; ox = ox > 0.f ? ox : expm1f(ox);
    float oy = accy * inv + bi.y; oy = oy > 0.f ? oy : expm1f(oy);
    ((float2*)out)[(size_t)d * 32 + lane] = make_float2(ox, oy);
}

__global__ void k_pool(const void* batch) {
    int i = blockIdx.x * blockDim.x + threadIdx.x;
    if (i >= NN * 64) return;
    int n = i >> 6, c = i & 63;
    int g = g_is64 ? (int)((const long long*)batch)[n] : ((const int*)batch)[n];
    atomicAdd(&g_pool[g * 64 + c], g_h[i]);
    if (c == 0) atomicAdd(&g_cnt[g], 1.0f);
}

__global__ void k_final(const float* __restrict__ lw, const float* __restrict__ lb,
                        float* __restrict__ out) {
    int tid = threadIdx.x;
    if (tid >= 128) return;
    int g = tid >> 1, k = tid & 1;
    float cnt = g_cnt[g]; cnt = cnt > 1.f ? cnt : 1.f;
    float s = 0.f;
    #pragma unroll 8
    for (int c = 0; c < 64; c++) s += (g_pool[g * 64 + c] / cnt) * lw[c * 2 + k];
    out[g * 2 + k] = s + lb[k];
}

extern "C" void kernel_launch(void* const* d_in, const int* in_sizes, int n_in,
                              void* d_out, int out_size) {
    const float* x     = (const float*)d_in[0];
    const void*  ei    = d_in[1];
    const void*  batch = d_in[2];
    const float* Wl1   = (const float*)d_in[3];
    const float* Wr1   = (const float*)d_in[4];
    const float* att1  = (const float*)d_in[5];
    const float* b1    = (const float*)d_in[6];
    const float* Wl2   = (const float*)d_in[7];
    const float* Wr2   = (const float*)d_in[8];
    const float* att2  = (const float*)d_in[9];
    const float* b2    = (const float*)d_in[10];
    const float* lb    = (const float*)d_in[12];
    const float* lw    = (const float*)d_in[11];
    float* out = (float*)d_out;

    float *xl, *xr, *h;
    cudaGetSymbolAddress((void**)&xl, g_xl);
    cudaGetSymbolAddress((void**)&xr, g_xr);
    cudaGetSymbolAddress((void**)&h,  g_h);

    const int TB = 256;
    const int GB_EDGE = (NE + TB - 1) / TB;     // 6250
    const int GB_NODE = (NN * 64 + TB - 1) / TB;
    const int GB_GAT  = (NN + 7) / 8;           // 6250 (8 warps/block)
    const int GB_GEMM = (NN + 63) / 64;         // 782

    const int SM128 = (128 * 64 + 64 * 128) * 4;  // 65536
    const int SM64  = (64 * 64 + 64 * 64) * 4;    // 32768
    cudaFuncSetAttribute(k_gemm2<128>, cudaFuncAttributeMaxDynamicSharedMemorySize, SM128);
    cudaFuncSetAttribute(k_gemm2<64>,  cudaFuncAttributeMaxDynamicSharedMemorySize, SM64);

    // CSR build (shared by both layers)
    k_detect<<<1, 32>>>(ei);
    k_zero<<<(NN + TB - 1) / TB, TB>>>();
    k_hist<<<GB_EDGE, TB>>>(ei);
    k_scan<<<1, 1024>>>();
    k_scatter<<<GB_EDGE, TB>>>(ei);

    // ---- layer 1 (heads=2, ch=32) ----
    k_gemm2<128><<<GB_GEMM, TB, SM128>>>(x, Wl1, xl);
    k_gemm2<128><<<GB_GEMM, TB, SM128>>>(x, Wr1, xr);
    k_gat<2><<<GB_GAT, TB>>>(xl, xr, att1, b1, h);

    // ---- layer 2 (heads=1, ch=64) ----
    k_gemm2<64><<<GB_GEMM, TB, SM64>>>(h, Wl2, xl);
    k_gemm2<64><<<GB_GEMM, TB, SM64>>>(h, Wr2, xr);
    k_gat<1><<<GB_GAT, TB>>>(xl, xr, att2, b2, h);

    // ---- pooling + classifier ----
    k_pool<<<GB_NODE, TB>>>(batch);
    k_final<<<1, 128>>>(lw, lb, out);
}

// round 5
// speedup vs baseline: 3.0118x; 1.4310x over previous
#include <cuda_runtime.h>
#include <math.h>

#define NN 50000
#define NE 1600000
#define NG 64
#define NB 196   // (NN+255)/256

// ---------------- device scratch ----------------
__device__ int   g_is64;
__device__ __align__(256) float g_xl[NN * 64];
__device__ __align__(256) float g_xr[NN * 64];
__device__ __align__(256) float g_h [NN * 64];
__device__ int   g_deg[NN];
__device__ int   g_off[NN + 1];
__device__ int   g_wp [NN];
__device__ int   g_csr[NE];
__device__ int   g_bsum[256];
__device__ float g_pool[NG * 64];
__device__ float g_cnt[NG];

// Detect int64 vs int32 edge_index (odd int32 words all zero for int64).
__global__ void k_detect(const void* ei) {
    if (threadIdx.x == 0) {
        const int* p = (const int*)ei;
        int nz = 0;
        #pragma unroll 4
        for (int i = 0; i < 128; i++) nz |= p[2 * i + 1];
        g_is64 = (nz == 0) ? 1 : 0;
    }
}

__device__ __forceinline__ int edge_src(const void* ei, int e, int is64) {
    return is64 ? (int)((const long long*)ei)[e] : ((const int*)ei)[e];
}
__device__ __forceinline__ int edge_dst(const void* ei, int e, int is64) {
    return is64 ? (int)((const long long*)ei)[NE + e] : ((const int*)ei)[NE + e];
}

__global__ void k_zero() {
    int i = blockIdx.x * blockDim.x + threadIdx.x;
    if (i < NN) g_deg[i] = 0;
    if (i < NG * 64) g_pool[i] = 0.f;
    if (i < NG) g_cnt[i] = 0.f;
}

__global__ void k_hist(const void* ei) {
    int e = blockIdx.x * blockDim.x + threadIdx.x;
    if (e < NE) atomicAdd(&g_deg[edge_dst(ei, e, g_is64)], 1);
}

// ---- three-pass coalesced exclusive scan of g_deg -> g_off / g_wp ----
__global__ void k_scan1() {
    __shared__ int sh[256];
    int t = threadIdx.x;
    int i = blockIdx.x * 256 + t;
    sh[t] = (i < NN) ? g_deg[i] : 0;
    __syncthreads();
    for (int off = 128; off; off >>= 1) {
        if (t < off) sh[t] += sh[t + off];
        __syncthreads();
    }
    if (t == 0) g_bsum[blockIdx.x] = sh[0];
}

__global__ void k_scan2() {
    __shared__ int sh[256];
    int t = threadIdx.x;
    int v = (t < NB) ? g_bsum[t] : 0;
    sh[t] = v;
    __syncthreads();
    for (int off = 1; off < 256; off <<= 1) {
        int u = (t >= off) ? sh[t - off] : 0;
        __syncthreads();
        sh[t] += u;
        __syncthreads();
    }
    if (t < NB) g_bsum[t] = sh[t] - v;       // exclusive
    if (t == 255) g_off[NN] = sh[255];
}

__global__ void k_scan3() {
    __shared__ int sh[256];
    int t = threadIdx.x;
    int i = blockIdx.x * 256 + t;
    int v = (i < NN) ? g_deg[i] : 0;
    sh[t] = v;
    __syncthreads();
    for (int off = 1; off < 256; off <<= 1) {
        int u = (t >= off) ? sh[t - off] : 0;
        __syncthreads();
        sh[t] += u;
        __syncthreads();
    }
    int excl = sh[t] - v + g_bsum[blockIdx.x];
    if (i < NN) { g_off[i] = excl; g_wp[i] = excl; }
}

__global__ void k_scatter(const void* ei) {
    int e = blockIdx.x * blockDim.x + threadIdx.x;
    if (e < NE) {
        int is64 = g_is64;
        int d = edge_dst(ei, e, is64);
        int s = edge_src(ei, e, is64);
        int p = atomicAdd(&g_wp[d], 1);
        g_csr[p] = s;
    }
}

// Y[N,64] = X[N,K] @ W[K,64]. 256 threads, 128 rows/block,
// each thread: 4 rows (n, n+32, n+64, n+96) x 8 cols. Padded x stride K+4.
template<int K>
__global__ void k_gemm4(const float* __restrict__ X, const float* __restrict__ W,
                        float* __restrict__ Y) {
    extern __shared__ float sm[];
    const int KP = K + 4;
    float* Ws = sm;                 // K*64
    float* xs = sm + K * 64;        // 128*(K+4)
    int tid = threadIdx.x;
    int n0  = blockIdx.x * 128;
    for (int i = tid; i < K * 16; i += 256)
        ((float4*)Ws)[i] = ((const float4*)W)[i];
    for (int i = tid; i < 32 * K; i += 256) {        // 128*K/4 float4 tiles
        int r = i / (K / 4), kk = i % (K / 4);
        int row = n0 + r;
        float4 v = (row < NN) ? ((const float4*)X)[(size_t)row * (K / 4) + kk]
                              : make_float4(0.f, 0.f, 0.f, 0.f);
        *(float4*)&xs[r * KP + kk * 4] = v;
    }
    __syncthreads();
    int n = tid >> 3, c0 = (tid & 7) * 8;
    float a[32];
    #pragma unroll
    for (int i = 0; i < 32; i++) a[i] = 0.f;
    #pragma unroll 2
    for (int k = 0; k < K; k++) {
        float4 w0 = *(const float4*)&Ws[k * 64 + c0];
        float4 w1 = *(const float4*)&Ws[k * 64 + c0 + 4];
        float x0 = xs[n * KP + k];
        float x1 = xs[(n + 32) * KP + k];
        float x2 = xs[(n + 64) * KP + k];
        float x3 = xs[(n + 96) * KP + k];
        a[0] += x0*w0.x; a[1] += x0*w0.y; a[2] += x0*w0.z; a[3] += x0*w0.w;
        a[4] += x0*w1.x; a[5] += x0*w1.y; a[6] += x0*w1.z; a[7] += x0*w1.w;
        a[8] += x1*w0.x; a[9] += x1*w0.y; a[10]+= x1*w0.z; a[11]+= x1*w0.w;
        a[12]+= x1*w1.x; a[13]+= x1*w1.y; a[14]+= x1*w1.z; a[15]+= x1*w1.w;
        a[16]+= x2*w0.x; a[17]+= x2*w0.y; a[18]+= x2*w0.z; a[19]+= x2*w0.w;
        a[20]+= x2*w1.x; a[21]+= x2*w1.y; a[22]+= x2*w1.z; a[23]+= x2*w1.w;
        a[24]+= x3*w0.x; a[25]+= x3*w0.y; a[26]+= x3*w0.z; a[27]+= x3*w0.w;
        a[28]+= x3*w1.x; a[29]+= x3*w1.y; a[30]+= x3*w1.z; a[31]+= x3*w1.w;
    }
    #pragma unroll
    for (int r = 0; r < 4; r++) {
        int row = n0 + n + r * 32;
        if (row < NN) {
            float4* y = (float4*)&Y[(size_t)row * 64 + c0];
            y[0] = make_float4(a[r*8+0], a[r*8+1], a[r*8+2], a[r*8+3]);
            y[1] = make_float4(a[r*8+4], a[r*8+5], a[r*8+6], a[r*8+7]);
        }
    }
}

// Fused GATv2: one warp per dst, 2 edges per iteration (half-warps), online
// softmax, no atomics. Lane holds 4 channels (float4). Head = (lane&15)>>3
// for NH=2; butterfly xor 1,2,4 (+8 for NH=1) stays within head groups.
template<int NH>
__global__ void k_gat(const float* __restrict__ xl, const float* __restrict__ xr,
                      const float* __restrict__ att, const float* __restrict__ bias,
                      float* __restrict__ out) {
    int w    = (blockIdx.x * blockDim.x + threadIdx.x) >> 5;
    int lane = threadIdx.x & 31;
    if (w >= NN) return;
    const int d = w;
    const int half = lane >> 4, li = lane & 15;
    const float4* XL = (const float4*)xl;
    float4 at  = ((const float4*)att)[li];
    float4 xrd = ((const float4*)xr)[(size_t)d * 16 + li];

    float m = -1e30f, ssum = 0.f;
    float4 acc = make_float4(0.f, 0.f, 0.f, 0.f);

#define GAT_PROC(cur, valid)                                                  \
    {                                                                         \
        float vx = (cur).x + xrd.x; vx = vx > 0.f ? vx : 0.2f * vx;           \
        float vy = (cur).y + xrd.y; vy = vy > 0.f ? vy : 0.2f * vy;           \
        float vz = (cur).z + xrd.z; vz = vz > 0.f ? vz : 0.2f * vz;           \
        float vw = (cur).w + xrd.w; vw = vw > 0.f ? vw : 0.2f * vw;           \
        float p = vx * at.x + vy * at.y + vz * at.z + vw * at.w;              \
        p += __shfl_xor_sync(0xffffffffu, p, 1);                              \
        p += __shfl_xor_sync(0xffffffffu, p, 2);                              \
        p += __shfl_xor_sync(0xffffffffu, p, 4);                              \
        if (NH == 1) p += __shfl_xor_sync(0xffffffffu, p, 8);                 \
        float nm  = (valid) ? fmaxf(m, p) : m;                                \
        float sc  = __expf(m - nm);                                           \
        float wgt = (valid) ? __expf(p - nm) : 0.f;                           \
        ssum = ssum * sc + wgt;                                               \
        acc.x = acc.x * sc + wgt * (cur).x;                                   \
        acc.y = acc.y * sc + wgt * (cur).y;                                   \
        acc.z = acc.z * sc + wgt * (cur).z;                                   \
        acc.w = acc.w * sc + wgt * (cur).w;                                   \
        m = nm;                                                               \
    }

    // self loop: valid in half A only (half B stays neutral)
    {
        float4 cur = XL[(size_t)d * 16 + li];
        GAT_PROC(cur, half == 0);
    }

    int start = g_off[d], end = g_off[d + 1];
    for (int j = start; j < end; j += 32) {
        int cnt = min(32, end - j);
        int sv = (j + lane < end) ? g_csr[j + lane] : 0;
        for (int k = 0; k < cnt; k += 2) {
            int idx = k + half;                       // edge within chunk
            int s = __shfl_sync(0xffffffffu, sv, idx & 31);
            bool valid = idx < cnt;
            float4 cur = XL[(size_t)(valid ? s : d) * 16 + li];
            GAT_PROC(cur, valid);
        }
    }
#undef GAT_PROC

    // merge half-warp softmax states (xor 16: same channels, same head)
    float mO = __shfl_xor_sync(0xffffffffu, m, 16);
    float sO = __shfl_xor_sync(0xffffffffu, ssum, 16);
    float aOx = __shfl_xor_sync(0xffffffffu, acc.x, 16);
    float aOy = __shfl_xor_sync(0xffffffffu, acc.y, 16);
    float aOz = __shfl_xor_sync(0xffffffffu, acc.z, 16);
    float aOw = __shfl_xor_sync(0xffffffffu, acc.w, 16);
    float nm = fmaxf(m, mO);
    float c1 = __expf(m - nm), c2 = __expf(mO - nm);
    float s  = ssum * c1 + sO * c2;
    float inv = 1.f / (s + 1e-16f);
    if (half == 0) {
        float4 bi = ((const float4*)bias)[li];
        float ox = (acc.x * c1 + aOx * c2) * inv + bi.x;
        float oy = (acc.y * c1 + aOy * c2) * inv + bi.y;
        float oz = (acc.z * c1 + aOz * c2) * inv + bi.z;
        float ow = (acc.w * c1 + aOw * c2) * inv + bi.w;
        ox = ox > 0.f ? ox : expm1f(ox);
        oy = oy > 0.f ? oy : expm1f(oy);
        oz = oz > 0.f ? oz : expm1f(oz);
        ow = ow > 0.f ? ow : expm1f(ow);
        ((float4*)out)[(size_t)d * 16 + li] = make_float4(ox, oy, oz, ow);
    }
}

__global__ void k_pool(const void* batch) {
    int i = blockIdx.x * blockDim.x + threadIdx.x;
    if (i >= NN * 64) return;
    int n = i >> 6, c = i & 63;
    int g = g_is64 ? (int)((const long long*)batch)[n] : ((const int*)batch)[n];
    atomicAdd(&g_pool[g * 64 + c], g_h[i]);
    if (c == 0) atomicAdd(&g_cnt[g], 1.0f);
}

__global__ void k_final(const float* __restrict__ lw, const float* __restrict__ lb,
                        float* __restrict__ out) {
    int tid = threadIdx.x;
    if (tid >= 128) return;
    int g = tid >> 1, k = tid & 1;
    float cnt = g_cnt[g]; cnt = cnt > 1.f ? cnt : 1.f;
    float s = 0.f;
    #pragma unroll 8
    for (int c = 0; c < 64; c++) s += (g_pool[g * 64 + c] / cnt) * lw[c * 2 + k];
    out[g * 2 + k] = s + lb[k];
}

extern "C" void kernel_launch(void* const* d_in, const int* in_sizes, int n_in,
                              void* d_out, int out_size) {
    const float* x     = (const float*)d_in[0];
    const void*  ei    = d_in[1];
    const void*  batch = d_in[2];
    const float* Wl1   = (const float*)d_in[3];
    const float* Wr1   = (const float*)d_in[4];
    const float* att1  = (const float*)d_in[5];
    const float* b1    = (const float*)d_in[6];
    const float* Wl2   = (const float*)d_in[7];
    const float* Wr2   = (const float*)d_in[8];
    const float* att2  = (const float*)d_in[9];
    const float* b2    = (const float*)d_in[10];
    const float* lw    = (const float*)d_in[11];
    const float* lb    = (const float*)d_in[12];
    float* out = (float*)d_out;

    float *xl, *xr, *h;
    cudaGetSymbolAddress((void**)&xl, g_xl);
    cudaGetSymbolAddress((void**)&xr, g_xr);
    cudaGetSymbolAddress((void**)&h,  g_h);

    const int TB = 256;
    const int GB_EDGE  = (NE + TB - 1) / TB;      // 6250
    const int GB_NODE  = (NN * 64 + TB - 1) / TB;
    const int GB_GAT   = (NN + 7) / 8;            // 6250
    const int GB_GEMM  = (NN + 127) / 128;        // 391

    const int SM128 = (128 * 64 + 128 * (128 + 4)) * 4;   // 100352
    const int SM64  = (64 * 64 + 128 * (64 + 4)) * 4;     // 51200
    cudaFuncSetAttribute(k_gemm4<128>, cudaFuncAttributeMaxDynamicSharedMemorySize, SM128);
    cudaFuncSetAttribute(k_gemm4<64>,  cudaFuncAttributeMaxDynamicSharedMemorySize, SM64);

    // CSR build (shared by both layers)
    k_detect<<<1, 32>>>(ei);
    k_zero<<<(NN + TB - 1) / TB, TB>>>();
    k_hist<<<GB_EDGE, TB>>>(ei);
    k_scan1<<<NB, 256>>>();
    k_scan2<<<1, 256>>>();
    k_scan3<<<NB, 256>>>();
    k_scatter<<<GB_EDGE, TB>>>(ei);

    // ---- layer 1 (heads=2, ch=32) ----
    k_gemm4<128><<<GB_GEMM, TB, SM128>>>(x, Wl1, xl);
    k_gemm4<128><<<GB_GEMM, TB, SM128>>>(x, Wr1, xr);
    k_gat<2><<<GB_GAT, TB>>>(xl, xr, att1, b1, h);

    // ---- layer 2 (heads=1, ch=64) ----
    k_gemm4<64><<<GB_GEMM, TB, SM64>>>(h, Wl2, xl);
    k_gemm4<64><<<GB_GEMM, TB, SM64>>>(h, Wr2, xr);
    k_gat<1><<<GB_GAT, TB>>>(xl, xr, att2, b2, h);

    // ---- pooling + classifier ----
    k_pool<<<GB_NODE, TB>>>(batch);
    k_final<<<1, 128>>>(lw, lb, out);
}

// round 7
// speedup vs baseline: 3.5600x; 1.1820x over previous
#include <cuda_runtime.h>
#include <math.h>

#define NN 50000
#define NE 1600000
#define NG 64
#define NB 196   // (NN+255)/256

// ---------------- device scratch ----------------
__device__ int   g_is64;
__device__ __align__(256) float g_xl[NN * 64];
__device__ __align__(256) float g_xr[NN * 64];
__device__ __align__(256) float g_h [NN * 64];
__device__ int   g_deg[NN];
__device__ int   g_off[NN + 1];
__device__ int   g_wp [NN];
__device__ int   g_csr[NE];
__device__ int   g_bsum[256];

// Detect int64 vs int32 edge_index (odd int32 words all zero for int64).
__global__ void k_detect(const void* ei) {
    if (threadIdx.x == 0) {
        const int* p = (const int*)ei;
        int nz = 0;
        #pragma unroll 4
        for (int i = 0; i < 128; i++) nz |= p[2 * i + 1];
        g_is64 = (nz == 0) ? 1 : 0;
    }
}

__device__ __forceinline__ int edge_src(const void* ei, int e, int is64) {
    return is64 ? (int)((const long long*)ei)[e] : ((const int*)ei)[e];
}
__device__ __forceinline__ int edge_dst(const void* ei, int e, int is64) {
    return is64 ? (int)((const long long*)ei)[NE + e] : ((const int*)ei)[NE + e];
}

__global__ void k_zero() {
    int i = blockIdx.x * blockDim.x + threadIdx.x;
    if (i < NN) g_deg[i] = 0;
}

__global__ void k_hist(const void* ei) {
    int e = blockIdx.x * blockDim.x + threadIdx.x;
    if (e < NE) atomicAdd(&g_deg[edge_dst(ei, e, g_is64)], 1);
}

// ---- three-pass coalesced exclusive scan of g_deg -> g_off / g_wp ----
__global__ void k_scan1() {
    __shared__ int sh[256];
    int t = threadIdx.x;
    int i = blockIdx.x * 256 + t;
    sh[t] = (i < NN) ? g_deg[i] : 0;
    __syncthreads();
    for (int off = 128; off; off >>= 1) {
        if (t < off) sh[t] += sh[t + off];
        __syncthreads();
    }
    if (t == 0) g_bsum[blockIdx.x] = sh[0];
}

__global__ void k_scan2() {
    __shared__ int sh[256];
    int t = threadIdx.x;
    int v = (t < NB) ? g_bsum[t] : 0;
    sh[t] = v;
    __syncthreads();
    for (int off = 1; off < 256; off <<= 1) {
        int u = (t >= off) ? sh[t - off] : 0;
        __syncthreads();
        sh[t] += u;
        __syncthreads();
    }
    if (t < NB) g_bsum[t] = sh[t] - v;       // exclusive
    if (t == 255) g_off[NN] = sh[255];
}

__global__ void k_scan3() {
    __shared__ int sh[256];
    int t = threadIdx.x;
    int i = blockIdx.x * 256 + t;
    int v = (i < NN) ? g_deg[i] : 0;
    sh[t] = v;
    __syncthreads();
    for (int off = 1; off < 256; off <<= 1) {
        int u = (t >= off) ? sh[t - off] : 0;
        __syncthreads();
        sh[t] += u;
        __syncthreads();
    }
    int excl = sh[t] - v + g_bsum[blockIdx.x];
    if (i < NN) { g_off[i] = excl; g_wp[i] = excl; }
}

__global__ void k_scatter(const void* ei) {
    int e = blockIdx.x * blockDim.x + threadIdx.x;
    if (e < NE) {
        int is64 = g_is64;
        int d = edge_dst(ei, e, is64);
        int s = edge_src(ei, e, is64);
        int p = atomicAdd(&g_wp[d], 1);
        g_csr[p] = s;
    }
}

// Fused dual GEMM: Yl = X@Wl, Yr = X@Wr. 256 threads, 128 rows/block,
// each thread 4 rows x 8 cols x 2 outputs. Padded x stride K+4.
template<int K>
__global__ void __launch_bounds__(256, 1)
k_gemmF(const float* __restrict__ X, const float* __restrict__ Wl,
        const float* __restrict__ Wr, float* __restrict__ Yl,
        float* __restrict__ Yr) {
    extern __shared__ float sm[];
    const int KP = K + 4;
    float* Wsl = sm;                  // K*64
    float* Wsr = sm + K * 64;         // K*64
    float* xs  = sm + 2 * K * 64;     // 128*(K+4)
    int tid = threadIdx.x;
    int n0  = blockIdx.x * 128;
    for (int i = tid; i < K * 16; i += 256) {
        ((float4*)Wsl)[i] = ((const float4*)Wl)[i];
        ((float4*)Wsr)[i] = ((const float4*)Wr)[i];
    }
    for (int i = tid; i < 32 * K; i += 256) {
        int r = i / (K / 4), kk = i % (K / 4);
        int row = n0 + r;
        float4 v = (row < NN) ? ((const float4*)X)[(size_t)row * (K / 4) + kk]
                              : make_float4(0.f, 0.f, 0.f, 0.f);
        *(float4*)&xs[r * KP + kk * 4] = v;
    }
    __syncthreads();
    int n = tid >> 3, c0 = (tid & 7) * 8;
    float al[32], ar[32];
    #pragma unroll
    for (int i = 0; i < 32; i++) { al[i] = 0.f; ar[i] = 0.f; }
    for (int k = 0; k < K; k++) {
        float4 l0 = *(const float4*)&Wsl[k * 64 + c0];
        float4 l1 = *(const float4*)&Wsl[k * 64 + c0 + 4];
        float4 r0 = *(const float4*)&Wsr[k * 64 + c0];
        float4 r1 = *(const float4*)&Wsr[k * 64 + c0 + 4];
        #pragma unroll
        for (int r = 0; r < 4; r++) {
            float xv = xs[(n + r * 32) * KP + k];
            al[r*8+0] += xv*l0.x; al[r*8+1] += xv*l0.y;
            al[r*8+2] += xv*l0.z; al[r*8+3] += xv*l0.w;
            al[r*8+4] += xv*l1.x; al[r*8+5] += xv*l1.y;
            al[r*8+6] += xv*l1.z; al[r*8+7] += xv*l1.w;
            ar[r*8+0] += xv*r0.x; ar[r*8+1] += xv*r0.y;
            ar[r*8+2] += xv*r0.z; ar[r*8+3] += xv*r0.w;
            ar[r*8+4] += xv*r1.x; ar[r*8+5] += xv*r1.y;
            ar[r*8+6] += xv*r1.z; ar[r*8+7] += xv*r1.w;
        }
    }
    #pragma unroll
    for (int r = 0; r < 4; r++) {
        int row = n0 + n + r * 32;
        if (row < NN) {
            float4* yl = (float4*)&Yl[(size_t)row * 64 + c0];
            yl[0] = make_float4(al[r*8+0], al[r*8+1], al[r*8+2], al[r*8+3]);
            yl[1] = make_float4(al[r*8+4], al[r*8+5], al[r*8+6], al[r*8+7]);
            float4* yr = (float4*)&Yr[(size_t)row * 64 + c0];
            yr[0] = make_float4(ar[r*8+0], ar[r*8+1], ar[r*8+2], ar[r*8+3]);
            yr[1] = make_float4(ar[r*8+4], ar[r*8+5], ar[r*8+6], ar[r*8+7]);
        }
    }
}

// Fused GATv2: one warp per dst node, 4 edges/iteration (8-lane quarters),
// softmax with fixed base = self-loop score (no online max rescale).
// Lane li (0..7) of each quarter holds channels 4li..4li+3 (v0, head0 for
// NH=2) and 32+4li..32+4li+3 (v1, head1 for NH=2).
template<int NH>
__global__ void k_gat(const float4* __restrict__ XL, const float4* __restrict__ XR,
                      const float* __restrict__ att, const float* __restrict__ bias,
                      float4* __restrict__ out) {
    int w    = (blockIdx.x * blockDim.x + threadIdx.x) >> 5;
    int lane = threadIdx.x & 31;
    if (w >= NN) return;
    const int d = w;
    const int q = lane >> 3, li = lane & 7;
    const unsigned FULL = 0xffffffffu;

    float4 at0 = ((const float4*)att)[li];
    float4 at1 = ((const float4*)att)[8 + li];
    float4 xr0 = XR[(size_t)d * 16 + li];
    float4 xr1 = XR[(size_t)d * 16 + 8 + li];

    float base0, base1;
    float ssum0 = 0.f, ssum1 = 0.f;
    float4 acc0 = make_float4(0.f, 0.f, 0.f, 0.f);
    float4 acc1 = make_float4(0.f, 0.f, 0.f, 0.f);

#define LRELU(a) ((a) > 0.f ? (a) : 0.2f * (a))
#define SCORE(v0, v1, P0, P1)                                                 \
    {                                                                         \
        float pa = LRELU((v0).x + xr0.x) * at0.x                              \
                 + LRELU((v0).y + xr0.y) * at0.y                              \
                 + LRELU((v0).z + xr0.z) * at0.z                              \
                 + LRELU((v0).w + xr0.w) * at0.w;                             \
        float pb = LRELU((v1).x + xr1.x) * at1.x                              \
                 + LRELU((v1).y + xr1.y) * at1.y                              \
                 + LRELU((v1).z + xr1.z) * at1.z                              \
                 + LRELU((v1).w + xr1.w) * at1.w;                             \
        if (NH == 1) {                                                        \
            float p = pa + pb;                                                \
            p += __shfl_xor_sync(FULL, p, 1);                                 \
            p += __shfl_xor_sync(FULL, p, 2);                                 \
            p += __shfl_xor_sync(FULL, p, 4);                                 \
            P0 = p; P1 = p;                                                   \
        } else {                                                              \
            float u = (li & 1) ? pb : pa;                                     \
            float t = (li & 1) ? pa : pb;                                     \
            u += __shfl_xor_sync(FULL, t, 1);                                 \
            u += __shfl_xor_sync(FULL, u, 2);                                 \
            u += __shfl_xor_sync(FULL, u, 4);                                 \
            float o = __shfl_xor_sync(FULL, u, 1);                            \
            P0 = (li & 1) ? o : u;                                            \
            P1 = (li & 1) ? u : o;                                            \
        }                                                                     \
    }

    // self loop: all quarters compute score (identical); quarter 0 contributes
    {
        float4 s0 = XL[(size_t)d * 16 + li];
        float4 s1 = XL[(size_t)d * 16 + 8 + li];
        float p0, p1;
        SCORE(s0, s1, p0, p1);
        base0 = p0; base1 = p1;
        float e = (q == 0) ? 1.f : 0.f;   // exp(p - base) = 1
        ssum0 = e; ssum1 = e;
        acc0 = make_float4(e * s0.x, e * s0.y, e * s0.z, e * s0.w);
        acc1 = make_float4(e * s1.x, e * s1.y, e * s1.z, e * s1.w);
    }

    int start = g_off[d], end = g_off[d + 1];
    for (int j = start; j < end; j += 32) {
        int cnt = min(32, end - j);
        int sv = (j + lane < end) ? g_csr[j + lane] : d;
        for (int k = 0; k < cnt; k += 4) {
            int idx = k + q;
            int s = __shfl_sync(FULL, sv, idx & 31);
            bool valid = idx < cnt;
            float4 v0 = XL[(size_t)s * 16 + li];
            float4 v1 = XL[(size_t)s * 16 + 8 + li];
            float p0, p1;
            SCORE(v0, v1, p0, p1);
            float e0 = valid ? __expf(p0 - base0) : 0.f;
            float e1 = (NH == 2) ? (valid ? __expf(p1 - base1) : 0.f) : e0;
            ssum0 += e0; ssum1 += e1;
            acc0.x += e0 * v0.x; acc0.y += e0 * v0.y;
            acc0.z += e0 * v0.z; acc0.w += e0 * v0.w;
            acc1.x += e1 * v1.x; acc1.y += e1 * v1.y;
            acc1.z += e1 * v1.z; acc1.w += e1 * v1.w;
        }
    }
#undef SCORE
#undef LRELU

    // merge quarters (xor 8, 16)
#define MRG(x) { x += __shfl_xor_sync(FULL, x, 8); x += __shfl_xor_sync(FULL, x, 16); }
    MRG(ssum0)
    if (NH == 2) { MRG(ssum1) } else { ssum1 = ssum0; }
    MRG(acc0.x) MRG(acc0.y) MRG(acc0.z) MRG(acc0.w)
    MRG(acc1.x) MRG(acc1.y) MRG(acc1.z) MRG(acc1.w)
#undef MRG

    if (q == 0) {
        float inv0 = 1.f / (ssum0 + 1e-16f);
        float inv1 = 1.f / (ssum1 + 1e-16f);
        float4 bi0 = ((const float4*)bias)[li];
        float4 bi1 = ((const float4*)bias)[8 + li];
        float4 o0, o1;
        o0.x = acc0.x * inv0 + bi0.x; o0.y = acc0.y * inv0 + bi0.y;
        o0.z = acc0.z * inv0 + bi0.z; o0.w = acc0.w * inv0 + bi0.w;
        o1.x = acc1.x * inv1 + bi1.x; o1.y = acc1.y * inv1 + bi1.y;
        o1.z = acc1.z * inv1 + bi1.z; o1.w = acc1.w * inv1 + bi1.w;
        o0.x = o0.x > 0.f ? o0.x : expm1f(o0.x);
        o0.y = o0.y > 0.f ? o0.y : expm1f(o0.y);
        o0.z = o0.z > 0.f ? o0.z : expm1f(o0.z);
        o0.w = o0.w > 0.f ? o0.w : expm1f(o0.w);
        o1.x = o1.x > 0.f ? o1.x : expm1f(o1.x);
        o1.y = o1.y > 0.f ? o1.y : expm1f(o1.y);
        o1.z = o1.z > 0.f ? o1.z : expm1f(o1.z);
        o1.w = o1.w > 0.f ? o1.w : expm1f(o1.w);
        out[(size_t)d * 16 + li]     = o0;
        out[(size_t)d * 16 + 8 + li] = o1;
    }
}

// Pool + classifier: one block per graph (batch sorted), no atomics.
__global__ void k_poolfin(const void* batch, const float* __restrict__ lw,
                          const float* __restrict__ lb, float* __restrict__ out) {
    __shared__ float sh[256];
    int g = blockIdx.x;
    int t = threadIdx.x;
    int is64 = g_is64;
    // lower_bound(g) and lower_bound(g+1)
    int lo = 0, hi = NN;
    while (lo < hi) {
        int mid = (lo + hi) >> 1;
        int b = is64 ? (int)((const long long*)batch)[mid] : ((const int*)batch)[mid];
        if (b < g) lo = mid + 1; else hi = mid;
    }
    int lo2 = lo, hi2 = NN;
    while (lo2 < hi2) {
        int mid = (lo2 + hi2) >> 1;
        int b = is64 ? (int)((const long long*)batch)[mid] : ((const int*)batch)[mid];
        if (b < g + 1) lo2 = mid + 1; else hi2 = mid;
    }
    int beg = lo, endn = lo2;
    int c = t & 63, r0 = t >> 6;
    float acc = 0.f;
    for (int n = beg + r0; n < endn; n += 4) acc += g_h[(size_t)n * 64 + c];
    sh[t] = acc;
    __syncthreads();
    if (t < 64) {
        float s = sh[t] + sh[t + 64] + sh[t + 128] + sh[t + 192];
        float cnt = (float)(endn - beg);
        cnt = cnt > 1.f ? cnt : 1.f;
        sh[t] = s / cnt;
    }
    __syncthreads();
    if (t < 2) {
        float s = 0.f;
        #pragma unroll 8
        for (int c2 = 0; c2 < 64; c2++) s += sh[c2] * lw[c2 * 2 + t];
        out[g * 2 + t] = s + lb[t];
    }
}

extern "C" void kernel_launch(void* const* d_in, const int* in_sizes, int n_in,
                              void* d_out, int out_size) {
    const float* x     = (const float*)d_in[0];
    const void*  ei    = d_in[1];
    const void*  batch = d_in[2];
    const float* Wl1   = (const float*)d_in[3];
    const float* Wr1   = (const float*)d_in[4];
    const float* att1  = (const float*)d_in[5];
    const float* b1    = (const float*)d_in[6];
    const float* Wl2   = (const float*)d_in[7];
    const float* Wr2   = (const float*)d_in[8];
    const float* att2  = (const float*)d_in[9];
    const float* b2    = (const float*)d_in[10];
    const float* lw    = (const float*)d_in[11];
    const float* lb    = (const float*)d_in[12];
    float* out = (float*)d_out;

    float *xl, *xr, *h;
    cudaGetSymbolAddress((void**)&xl, g_xl);
    cudaGetSymbolAddress((void**)&xr, g_xr);
    cudaGetSymbolAddress((void**)&h,  g_h);

    const int TB = 256;
    const int GB_EDGE = (NE + TB - 1) / TB;      // 6250
    const int GB_GAT  = (NN + 7) / 8;            // 6250
    const int GB_GEMM = (NN + 127) / 128;        // 391

    const int SMF128 = (2 * 128 * 64 + 128 * (128 + 4)) * 4;  // 133120
    const int SMF64  = (2 * 64 * 64 + 128 * (64 + 4)) * 4;    // 67584
    cudaFuncSetAttribute(k_gemmF<128>, cudaFuncAttributeMaxDynamicSharedMemorySize, SMF128);
    cudaFuncSetAttribute(k_gemmF<64>,  cudaFuncAttributeMaxDynamicSharedMemorySize, SMF64);

    // CSR build (shared by both layers)
    k_detect<<<1, 32>>>(ei);
    k_zero<<<NB, TB>>>();
    k_hist<<<GB_EDGE, TB>>>(ei);
    k_scan1<<<NB, 256>>>();
    k_scan2<<<1, 256>>>();
    k_scan3<<<NB, 256>>>();
    k_scatter<<<GB_EDGE, TB>>>(ei);

    // ---- layer 1 (heads=2, ch=32) ----
    k_gemmF<128><<<GB_GEMM, TB, SMF128>>>(x, Wl1, Wr1, xl, xr);
    k_gat<2><<<GB_GAT, TB>>>((const float4*)xl, (const float4*)xr, att1, b1, (float4*)h);

    // ---- layer 2 (heads=1, ch=64) ----
    k_gemmF<64><<<GB_GEMM, TB, SMF64>>>(h, Wl2, Wr2, xl, xr);
    k_gat<1><<<GB_GAT, TB>>>((const float4*)xl, (const float4*)xr, att2, b2, (float4*)h);

    // ---- pooling + classifier ----
    k_poolfin<<<NG, 256>>>(batch, lw, lb, out);
}